// round 1
// baseline (speedup 1.0000x reference)
#include <cuda_runtime.h>
#include <math.h>
#include <stdint.h>

// LinearSelfAttention: B=4, T=8192, D=512, H=8, HD=64
// out = x @ E_b + bias_b, where E_b = Wq^T BlockDiag(C_b) Wout^T,
// C_b[h] = (exp(K_h)^T V_h) / colsum(exp(K_h))   (softmax over T is separable)

#define B_ 4
#define T_ 8192
#define D_ 512
#define H_ 8
#define HD_ 64
#define TT_ 128            // token tile
#define NTILE_ (T_ / TT_)  // 64 tiles per batch

// ---------------- scratch (device globals; no allocs) ----------------
__device__ float g_Upart[B_ * NTILE_ * H_ * HD_ * HD_]; // [b][tile][h][d][v]  32 MB
__device__ float g_Spart[B_ * NTILE_ * H_ * HD_];       // [b][tile][h][d]
__device__ float g_C[B_ * H_ * HD_ * HD_];              // context [b][h][d][v]
__device__ float g_A[B_ * D_ * D_];                     // [b][j][i]
__device__ float g_E[B_ * D_ * D_];                     // [b][i][o]
__device__ float g_pb[B_ * D_];                         // q-bias pushed through C
__device__ float g_bias[B_ * D_];                       // final per-batch bias vec

// =====================================================================
// K1: fused KV projection + per-tile U/S.
// grid (64 tiles, 8 heads, 4 batch), block 256 (16x16), 8x8 microtile.
// Computes [128 tokens x 128 cols] where cols 0..63 = exp(k_h+bk), 64..127 = v_h+bv,
// then U_h = EK^T @ V (64x64) and S_h = colsum(EK).
// =====================================================================
__global__ __launch_bounds__(256, 2)
void k1_kv_context(const float* __restrict__ x,
                   const float* __restrict__ Wqkv,
                   const float* __restrict__ bqkv)
{
    const int tid = threadIdx.x;
    const int tx = tid & 15, ty = tid >> 4;
    const int tile = blockIdx.x, h = blockIdx.y, b = blockIdx.z;

    extern __shared__ float sm[];
    float* Xs = sm;              // [128][17]
    float* Ws = sm + 128 * 17;   // [128][17]

    const float* xb = x + (size_t)(b * T_ + tile * TT_) * D_;
    const int wrow_k = D_ + h * HD_;       // k rows in W_qkv
    const int wrow_v = 2 * D_ + h * HD_;   // v rows

    float acc[8][8];
    #pragma unroll
    for (int r = 0; r < 8; r++)
        #pragma unroll
        for (int c = 0; c < 8; c++) acc[r][c] = 0.f;

    for (int k0 = 0; k0 < D_; k0 += 16) {
        // load X tile [128][16]
        #pragma unroll
        for (int q = 0; q < 2; q++) {
            int flat = tid * 2 + q;          // 0..511 float4s
            int r = flat >> 2;
            int c4 = (flat & 3) * 4;
            float4 t = *reinterpret_cast<const float4*>(xb + (size_t)r * D_ + k0 + c4);
            float* dst = Xs + r * 17 + c4;
            dst[0] = t.x; dst[1] = t.y; dst[2] = t.z; dst[3] = t.w;
        }
        // load W tile [128 cols][16]: col<64 -> k rows, else v rows
        #pragma unroll
        for (int q = 0; q < 2; q++) {
            int flat = tid * 2 + q;
            int col = flat >> 2;
            int c4 = (flat & 3) * 4;
            int wrow = (col < 64) ? (wrow_k + col) : (wrow_v + col - 64);
            float4 t = *reinterpret_cast<const float4*>(Wqkv + (size_t)wrow * D_ + k0 + c4);
            float* dst = Ws + col * 17 + c4;
            dst[0] = t.x; dst[1] = t.y; dst[2] = t.z; dst[3] = t.w;
        }
        __syncthreads();
        #pragma unroll
        for (int kk = 0; kk < 16; kk++) {
            float a_[8], b_[8];
            #pragma unroll
            for (int r = 0; r < 8; r++) a_[r] = Xs[(ty * 8 + r) * 17 + kk];
            #pragma unroll
            for (int c = 0; c < 8; c++) b_[c] = Ws[(tx + 16 * c) * 17 + kk];
            #pragma unroll
            for (int r = 0; r < 8; r++)
                #pragma unroll
                for (int c = 0; c < 8; c++) acc[r][c] += a_[r] * b_[c];
        }
        __syncthreads();
    }

    // epilogue: bias, exp on k-half, stage into KV smem [128][129]
    float* KV = sm;
    #pragma unroll
    for (int r = 0; r < 8; r++) {
        #pragma unroll
        for (int c = 0; c < 8; c++) {
            int row = ty * 8 + r;
            int col = tx + 16 * c;
            float v = acc[r][c];
            if (col < 64) v = expf(v + bqkv[wrow_k + col]);
            else          v = v + bqkv[wrow_v + col - 64];
            KV[row * 129 + col] = v;
        }
    }
    __syncthreads();

    // U = EK^T @ V : threads 16x16, 4x4 microtile
    float u[4][4];
    #pragma unroll
    for (int dd = 0; dd < 4; dd++)
        #pragma unroll
        for (int vv = 0; vv < 4; vv++) u[dd][vv] = 0.f;

    for (int t = 0; t < TT_; t++) {
        float a_[4], b_[4];
        #pragma unroll
        for (int dd = 0; dd < 4; dd++) a_[dd] = KV[t * 129 + ty * 4 + dd];
        #pragma unroll
        for (int vv = 0; vv < 4; vv++) b_[vv] = KV[t * 129 + 64 + tx * 4 + vv];
        #pragma unroll
        for (int dd = 0; dd < 4; dd++)
            #pragma unroll
            for (int vv = 0; vv < 4; vv++) u[dd][vv] += a_[dd] * b_[vv];
    }
    size_t ubase = (size_t)((b * NTILE_ + tile) * H_ + h) * (HD_ * HD_);
    #pragma unroll
    for (int dd = 0; dd < 4; dd++)
        #pragma unroll
        for (int vv = 0; vv < 4; vv++)
            g_Upart[ubase + (ty * 4 + dd) * HD_ + tx * 4 + vv] = u[dd][vv];

    if (tid < 64) {
        float s = 0.f;
        for (int t = 0; t < TT_; t++) s += KV[t * 129 + tid];
        g_Spart[((b * NTILE_ + tile) * H_ + h) * HD_ + tid] = s;
    }
}

// =====================================================================
// K2: deterministic reduction of partials -> context C = U / S
// grid 32 (b*h), block 256
// =====================================================================
__global__ void k2_reduce()
{
    const int b = blockIdx.x >> 3, h = blockIdx.x & 7;
    const int tid = threadIdx.x;
    __shared__ float S[64];
    if (tid < 64) {
        float s = 0.f;
        for (int t = 0; t < NTILE_; t++)
            s += g_Spart[((b * NTILE_ + t) * H_ + h) * HD_ + tid];
        S[tid] = s;
    }
    __syncthreads();
    for (int e = tid; e < HD_ * HD_; e += 256) {
        float u = 0.f;
        #pragma unroll 8
        for (int t = 0; t < NTILE_; t++)
            u += g_Upart[(size_t)((b * NTILE_ + t) * H_ + h) * (HD_ * HD_) + e];
        g_C[(b * H_ + h) * (HD_ * HD_) + e] = u / S[e >> 6];
    }
}

// =====================================================================
// K3: A[b][j=h*64+vv][i] = sum_d Wq[h*64+d][i] * C[b][h][d][vv]
// grid 32 (b*h), block 256
// =====================================================================
__global__ void k3_A(const float* __restrict__ Wqkv)
{
    const int b = blockIdx.x >> 3, h = blockIdx.x & 7;
    const int tid = threadIdx.x;
    __shared__ float Ch[64 * 64];
    __shared__ float Wc[64 * 128];
    for (int e = tid; e < 4096; e += 256)
        Ch[e] = g_C[(b * H_ + h) * 4096 + e];
    for (int chunk = 0; chunk < 4; chunk++) {
        int i0 = chunk * 128;
        __syncthreads();
        for (int e = tid; e < 64 * 128; e += 256) {
            int d = e >> 7, ii = e & 127;
            Wc[e] = Wqkv[(size_t)(h * HD_ + d) * D_ + i0 + ii];
        }
        __syncthreads();
        for (int idx = tid; idx < 64 * 128; idx += 256) {
            int vv = idx >> 7, ii = idx & 127;
            float s = 0.f;
            #pragma unroll
            for (int d = 0; d < 64; d++) s += Ch[d * 64 + vv] * Wc[d * 128 + ii];
            g_A[(size_t)b * (D_ * D_) + (size_t)(h * HD_ + vv) * D_ + i0 + ii] = s;
        }
    }
}

// K3b: push q-bias through blockdiag(C): pb[b][j] = sum_d bq[h*64+d]*C[b][h][d][vv]
__global__ void k3b_pb(const float* __restrict__ bqkv)
{
    const int b = blockIdx.x;
    const int j = threadIdx.x;
    const int h = j >> 6, vv = j & 63;
    float s = 0.f;
    for (int d = 0; d < 64; d++)
        s += bqkv[h * HD_ + d] * g_C[(b * H_ + h) * 4096 + d * 64 + vv];
    g_pb[b * D_ + j] = s;
}

// =====================================================================
// K4: E[b][i][o] = sum_j A[b][j][i] * Wout[o][j]
// grid (4 itile, 4 otile, 4 b), block 256, 128x128 tile
// =====================================================================
__global__ __launch_bounds__(256, 2)
void k4_E(const float* __restrict__ Wout)
{
    const int tid = threadIdx.x;
    const int tx = tid & 15, ty = tid >> 4;
    const int i0 = blockIdx.x * 128, o0 = blockIdx.y * 128, b = blockIdx.z;
    __shared__ float Xs[128 * 17];
    __shared__ float Ws[128 * 17];
    const float* Ab = g_A + (size_t)b * (D_ * D_);

    float acc[8][8];
    #pragma unroll
    for (int r = 0; r < 8; r++)
        #pragma unroll
        for (int c = 0; c < 8; c++) acc[r][c] = 0.f;

    for (int j0 = 0; j0 < D_; j0 += 16) {
        // Xs[ii][jj] = A[j0+jj][i0+ii] (transpose-on-load, float4 along ii)
        #pragma unroll
        for (int q = 0; q < 2; q++) {
            int flat = tid * 2 + q;         // 0..511
            int jj = flat >> 5;             // /32
            int ii = (flat & 31) * 4;
            float4 t = *reinterpret_cast<const float4*>(Ab + (size_t)(j0 + jj) * D_ + i0 + ii);
            Xs[(ii + 0) * 17 + jj] = t.x;
            Xs[(ii + 1) * 17 + jj] = t.y;
            Xs[(ii + 2) * 17 + jj] = t.z;
            Xs[(ii + 3) * 17 + jj] = t.w;
        }
        // Ws[col][jj] = Wout[o0+col][j0+jj]
        #pragma unroll
        for (int q = 0; q < 2; q++) {
            int flat = tid * 2 + q;
            int col = flat >> 2;
            int c4 = (flat & 3) * 4;
            float4 t = *reinterpret_cast<const float4*>(Wout + (size_t)(o0 + col) * D_ + j0 + c4);
            float* dst = Ws + col * 17 + c4;
            dst[0] = t.x; dst[1] = t.y; dst[2] = t.z; dst[3] = t.w;
        }
        __syncthreads();
        #pragma unroll
        for (int kk = 0; kk < 16; kk++) {
            float a_[8], b_[8];
            #pragma unroll
            for (int r = 0; r < 8; r++) a_[r] = Xs[(ty * 8 + r) * 17 + kk];
            #pragma unroll
            for (int c = 0; c < 8; c++) b_[c] = Ws[(tx + 16 * c) * 17 + kk];
            #pragma unroll
            for (int r = 0; r < 8; r++)
                #pragma unroll
                for (int c = 0; c < 8; c++) acc[r][c] += a_[r] * b_[c];
        }
        __syncthreads();
    }
    #pragma unroll
    for (int r = 0; r < 8; r++)
        #pragma unroll
        for (int c = 0; c < 8; c++)
            g_E[(size_t)b * (D_ * D_) + (size_t)(i0 + ty * 8 + r) * D_ + o0 + tx + 16 * c] = acc[r][c];
}

// K4b: bias_b[o] = b_out[o] + sum_j pb[b][j]*Wout[o][j]
__global__ void k4b_bias(const float* __restrict__ Wout, const float* __restrict__ bout)
{
    const int b = blockIdx.x;
    const int o = threadIdx.x;
    float s = bout[o];
    const float* wr = Wout + (size_t)o * D_;
    const float* pb = g_pb + b * D_;
    #pragma unroll 8
    for (int j = 0; j < D_; j++) s += pb[j] * wr[j];
    g_bias[b * D_ + o] = s;
}

// =====================================================================
// K5: out[b][t][o] = sum_i x[b][t][i]*E[b][i][o] + bias_b[o]
// grid (64 ttile, 4 otile, 4 b), block 256, 128x128 tile
// =====================================================================
__global__ __launch_bounds__(256, 2)
void k5_out(const float* __restrict__ x, float* __restrict__ out)
{
    const int tid = threadIdx.x;
    const int tx = tid & 15, ty = tid >> 4;
    const int t0 = blockIdx.x * 128, o0 = blockIdx.y * 128, b = blockIdx.z;
    __shared__ float Xs[128 * 17];
    __shared__ float Es[16 * 132];
    const float* xb = x + (size_t)(b * T_ + t0) * D_;
    const float* Eb = g_E + (size_t)b * (D_ * D_);

    float acc[8][8];
    #pragma unroll
    for (int r = 0; r < 8; r++)
        #pragma unroll
        for (int c = 0; c < 8; c++) acc[r][c] = 0.f;

    for (int i0 = 0; i0 < D_; i0 += 16) {
        #pragma unroll
        for (int q = 0; q < 2; q++) {
            int flat = tid * 2 + q;
            int r = flat >> 2;
            int c4 = (flat & 3) * 4;
            float4 t = *reinterpret_cast<const float4*>(xb + (size_t)r * D_ + i0 + c4);
            float* dst = Xs + r * 17 + c4;
            dst[0] = t.x; dst[1] = t.y; dst[2] = t.z; dst[3] = t.w;
        }
        // Es[kk][col] = E[i0+kk][o0+col], float4 along col (132 stride keeps 16B align)
        #pragma unroll
        for (int q = 0; q < 2; q++) {
            int flat = tid * 2 + q;          // 0..511
            int kk = flat >> 5;
            int c4 = (flat & 31) * 4;
            float4 t = *reinterpret_cast<const float4*>(Eb + (size_t)(i0 + kk) * D_ + o0 + c4);
            *reinterpret_cast<float4*>(Es + kk * 132 + c4) = t;
        }
        __syncthreads();
        #pragma unroll
        for (int kk = 0; kk < 16; kk++) {
            float a_[8], b_[8];
            #pragma unroll
            for (int r = 0; r < 8; r++) a_[r] = Xs[(ty * 8 + r) * 17 + kk];
            #pragma unroll
            for (int c = 0; c < 8; c++) b_[c] = Es[kk * 132 + tx + 16 * c];
            #pragma unroll
            for (int r = 0; r < 8; r++)
                #pragma unroll
                for (int c = 0; c < 8; c++) acc[r][c] += a_[r] * b_[c];
        }
        __syncthreads();
    }
    #pragma unroll
    for (int r = 0; r < 8; r++)
        #pragma unroll
        for (int c = 0; c < 8; c++) {
            int row = t0 + ty * 8 + r;
            int col = o0 + tx + 16 * c;
            out[(size_t)(b * T_ + row) * D_ + col] = acc[r][c] + g_bias[b * D_ + col];
        }
}

// =====================================================================
extern "C" void kernel_launch(void* const* d_in, const int* in_sizes, int n_in,
                              void* d_out, int out_size)
{
    (void)in_sizes; (void)n_in; (void)out_size;
    const float* x    = (const float*)d_in[0];
    const float* Wqkv = (const float*)d_in[1];
    const float* bqkv = (const float*)d_in[2];
    const float* Wout = (const float*)d_in[3];
    const float* bout = (const float*)d_in[4];
    float* out = (float*)d_out;

    const size_t K1_SMEM = 128 * 129 * sizeof(float); // 66048 B
    cudaFuncSetAttribute(k1_kv_context, cudaFuncAttributeMaxDynamicSharedMemorySize, (int)K1_SMEM);

    k1_kv_context<<<dim3(NTILE_, H_, B_), 256, K1_SMEM>>>(x, Wqkv, bqkv);
    k2_reduce<<<B_ * H_, 256>>>();
    k3_A<<<B_ * H_, 256>>>(Wqkv);
    k3b_pb<<<B_, D_>>>(bqkv);
    k4_E<<<dim3(4, 4, B_), 256>>>(Wout);
    k4b_bias<<<B_, D_>>>(Wout, bout);
    k5_out<<<dim3(NTILE_, 4, B_), 256>>>(x, out);
}

// round 9
// speedup vs baseline: 1.0859x; 1.0859x over previous
#include <cuda_runtime.h>
#include <cuda_bf16.h>
#include <mma.h>
#include <math.h>
#include <stdint.h>

using namespace nvcuda;

// LinearSelfAttention: B=4, T=8192, D=512, H=8, HD=64
// Round-1 passing kernel verbatim, with EXACTLY ONE change:
// k5_out replaced by a WMMA bf16 (3-term split) version that converts
// fp32 x / fp32 E to bf16 hi/lo inline while staging to smem.

#define B_ 4
#define T_ 8192
#define D_ 512
#define H_ 8
#define HD_ 64
#define TT_ 128            // token tile
#define NTILE_ (T_ / TT_)  // 64 tiles per batch
#define KC_ 32             // k-chunk for WMMA K5
#define NCH_ (D_ / KC_)    // 16
#define LDS_ 48            // smem row stride in bf16 (96B rows)

// ---------------- scratch (device globals; no allocs) ----------------
__device__ __align__(128) float g_Upart[B_ * NTILE_ * H_ * HD_ * HD_]; // 32 MB
__device__ __align__(128) float g_Spart[B_ * NTILE_ * H_ * HD_];
__device__ __align__(128) float g_C[B_ * H_ * HD_ * HD_];
__device__ __align__(128) float g_A[B_ * D_ * D_];
__device__ __align__(128) float g_E[B_ * D_ * D_];                     // [b][i][o]
__device__ __align__(128) float g_pb[B_ * D_];
__device__ __align__(128) float g_bias[B_ * D_];

// =====================================================================
// K1: fused KV projection + per-tile U/S.  (round-1 verbatim, SIMT)
// =====================================================================
__global__ __launch_bounds__(256, 2)
void k1_kv_context(const float* __restrict__ x,
                   const float* __restrict__ Wqkv,
                   const float* __restrict__ bqkv)
{
    const int tid = threadIdx.x;
    const int tx = tid & 15, ty = tid >> 4;
    const int tile = blockIdx.x, h = blockIdx.y, b = blockIdx.z;

    extern __shared__ float sm[];
    float* Xs = sm;              // [128][17]
    float* Ws = sm + 128 * 17;   // [128][17]

    const float* xb = x + (size_t)(b * T_ + tile * TT_) * D_;
    const int wrow_k = D_ + h * HD_;
    const int wrow_v = 2 * D_ + h * HD_;

    float acc[8][8];
    #pragma unroll
    for (int r = 0; r < 8; r++)
        #pragma unroll
        for (int c = 0; c < 8; c++) acc[r][c] = 0.f;

    for (int k0 = 0; k0 < D_; k0 += 16) {
        #pragma unroll
        for (int q = 0; q < 2; q++) {
            int flat = tid * 2 + q;
            int r = flat >> 2;
            int c4 = (flat & 3) * 4;
            float4 t = *reinterpret_cast<const float4*>(xb + (size_t)r * D_ + k0 + c4);
            float* dst = Xs + r * 17 + c4;
            dst[0] = t.x; dst[1] = t.y; dst[2] = t.z; dst[3] = t.w;
        }
        #pragma unroll
        for (int q = 0; q < 2; q++) {
            int flat = tid * 2 + q;
            int col = flat >> 2;
            int c4 = (flat & 3) * 4;
            int wrow = (col < 64) ? (wrow_k + col) : (wrow_v + col - 64);
            float4 t = *reinterpret_cast<const float4*>(Wqkv + (size_t)wrow * D_ + k0 + c4);
            float* dst = Ws + col * 17 + c4;
            dst[0] = t.x; dst[1] = t.y; dst[2] = t.z; dst[3] = t.w;
        }
        __syncthreads();
        #pragma unroll
        for (int kk = 0; kk < 16; kk++) {
            float a_[8], b_[8];
            #pragma unroll
            for (int r = 0; r < 8; r++) a_[r] = Xs[(ty * 8 + r) * 17 + kk];
            #pragma unroll
            for (int c = 0; c < 8; c++) b_[c] = Ws[(tx + 16 * c) * 17 + kk];
            #pragma unroll
            for (int r = 0; r < 8; r++)
                #pragma unroll
                for (int c = 0; c < 8; c++) acc[r][c] += a_[r] * b_[c];
        }
        __syncthreads();
    }

    float* KV = sm;
    #pragma unroll
    for (int r = 0; r < 8; r++) {
        #pragma unroll
        for (int c = 0; c < 8; c++) {
            int row = ty * 8 + r;
            int col = tx + 16 * c;
            float v = acc[r][c];
            if (col < 64) v = expf(v + bqkv[wrow_k + col]);
            else          v = v + bqkv[wrow_v + col - 64];
            KV[row * 129 + col] = v;
        }
    }
    __syncthreads();

    float u[4][4];
    #pragma unroll
    for (int dd = 0; dd < 4; dd++)
        #pragma unroll
        for (int vv = 0; vv < 4; vv++) u[dd][vv] = 0.f;

    for (int t = 0; t < TT_; t++) {
        float a_[4], b_[4];
        #pragma unroll
        for (int dd = 0; dd < 4; dd++) a_[dd] = KV[t * 129 + ty * 4 + dd];
        #pragma unroll
        for (int vv = 0; vv < 4; vv++) b_[vv] = KV[t * 129 + 64 + tx * 4 + vv];
        #pragma unroll
        for (int dd = 0; dd < 4; dd++)
            #pragma unroll
            for (int vv = 0; vv < 4; vv++) u[dd][vv] += a_[dd] * b_[vv];
    }
    size_t ubase = (size_t)((b * NTILE_ + tile) * H_ + h) * (HD_ * HD_);
    #pragma unroll
    for (int dd = 0; dd < 4; dd++)
        #pragma unroll
        for (int vv = 0; vv < 4; vv++)
            g_Upart[ubase + (ty * 4 + dd) * HD_ + tx * 4 + vv] = u[dd][vv];

    if (tid < 64) {
        float s = 0.f;
        for (int t = 0; t < TT_; t++) s += KV[t * 129 + tid];
        g_Spart[((b * NTILE_ + tile) * H_ + h) * HD_ + tid] = s;
    }
}

// =====================================================================
// K2: reduce partials -> C = U / S  (round-1 verbatim)
// =====================================================================
__global__ void k2_reduce()
{
    const int b = blockIdx.x >> 3, h = blockIdx.x & 7;
    const int tid = threadIdx.x;
    __shared__ float S[64];
    if (tid < 64) {
        float s = 0.f;
        for (int t = 0; t < NTILE_; t++)
            s += g_Spart[((b * NTILE_ + t) * H_ + h) * HD_ + tid];
        S[tid] = s;
    }
    __syncthreads();
    for (int e = tid; e < HD_ * HD_; e += 256) {
        float u = 0.f;
        #pragma unroll 8
        for (int t = 0; t < NTILE_; t++)
            u += g_Upart[(size_t)((b * NTILE_ + t) * H_ + h) * (HD_ * HD_) + e];
        g_C[(b * H_ + h) * (HD_ * HD_) + e] = u / S[e >> 6];
    }
}

// =====================================================================
// K3: A[b][j][i]  (round-1 verbatim)
// =====================================================================
__global__ void k3_A(const float* __restrict__ Wqkv)
{
    const int b = blockIdx.x >> 3, h = blockIdx.x & 7;
    const int tid = threadIdx.x;
    __shared__ float Ch[64 * 64];
    __shared__ float Wc[64 * 128];
    for (int e = tid; e < 4096; e += 256)
        Ch[e] = g_C[(b * H_ + h) * 4096 + e];
    for (int chunk = 0; chunk < 4; chunk++) {
        int i0 = chunk * 128;
        __syncthreads();
        for (int e = tid; e < 64 * 128; e += 256) {
            int d = e >> 7, ii = e & 127;
            Wc[e] = Wqkv[(size_t)(h * HD_ + d) * D_ + i0 + ii];
        }
        __syncthreads();
        for (int idx = tid; idx < 64 * 128; idx += 256) {
            int vv = idx >> 7, ii = idx & 127;
            float s = 0.f;
            #pragma unroll
            for (int d = 0; d < 64; d++) s += Ch[d * 64 + vv] * Wc[d * 128 + ii];
            g_A[(size_t)b * (D_ * D_) + (size_t)(h * HD_ + vv) * D_ + i0 + ii] = s;
        }
    }
}

__global__ void k3b_pb(const float* __restrict__ bqkv)
{
    const int b = blockIdx.x;
    const int j = threadIdx.x;
    const int h = j >> 6, vv = j & 63;
    float s = 0.f;
    for (int d = 0; d < 64; d++)
        s += bqkv[h * HD_ + d] * g_C[(b * H_ + h) * 4096 + d * 64 + vv];
    g_pb[b * D_ + j] = s;
}

// =====================================================================
// K4: E[b][i][o]  (round-1 verbatim, fp32)
// =====================================================================
__global__ __launch_bounds__(256, 2)
void k4_E(const float* __restrict__ Wout)
{
    const int tid = threadIdx.x;
    const int tx = tid & 15, ty = tid >> 4;
    const int i0 = blockIdx.x * 128, o0 = blockIdx.y * 128, b = blockIdx.z;
    __shared__ float Xs[128 * 17];
    __shared__ float Ws[128 * 17];
    const float* Ab = g_A + (size_t)b * (D_ * D_);

    float acc[8][8];
    #pragma unroll
    for (int r = 0; r < 8; r++)
        #pragma unroll
        for (int c = 0; c < 8; c++) acc[r][c] = 0.f;

    for (int j0 = 0; j0 < D_; j0 += 16) {
        #pragma unroll
        for (int q = 0; q < 2; q++) {
            int flat = tid * 2 + q;
            int jj = flat >> 5;
            int ii = (flat & 31) * 4;
            float4 t = *reinterpret_cast<const float4*>(Ab + (size_t)(j0 + jj) * D_ + i0 + ii);
            Xs[(ii + 0) * 17 + jj] = t.x;
            Xs[(ii + 1) * 17 + jj] = t.y;
            Xs[(ii + 2) * 17 + jj] = t.z;
            Xs[(ii + 3) * 17 + jj] = t.w;
        }
        #pragma unroll
        for (int q = 0; q < 2; q++) {
            int flat = tid * 2 + q;
            int col = flat >> 2;
            int c4 = (flat & 3) * 4;
            float4 t = *reinterpret_cast<const float4*>(Wout + (size_t)(o0 + col) * D_ + j0 + c4);
            float* dst = Ws + col * 17 + c4;
            dst[0] = t.x; dst[1] = t.y; dst[2] = t.z; dst[3] = t.w;
        }
        __syncthreads();
        #pragma unroll
        for (int kk = 0; kk < 16; kk++) {
            float a_[8], b_[8];
            #pragma unroll
            for (int r = 0; r < 8; r++) a_[r] = Xs[(ty * 8 + r) * 17 + kk];
            #pragma unroll
            for (int c = 0; c < 8; c++) b_[c] = Ws[(tx + 16 * c) * 17 + kk];
            #pragma unroll
            for (int r = 0; r < 8; r++)
                #pragma unroll
                for (int c = 0; c < 8; c++) acc[r][c] += a_[r] * b_[c];
        }
        __syncthreads();
    }
    #pragma unroll
    for (int r = 0; r < 8; r++)
        #pragma unroll
        for (int c = 0; c < 8; c++)
            g_E[(size_t)b * (D_ * D_) + (size_t)(i0 + ty * 8 + r) * D_ + o0 + tx + 16 * c] = acc[r][c];
}

__global__ void k4b_bias(const float* __restrict__ Wout, const float* __restrict__ bout)
{
    const int b = blockIdx.x;
    const int o = threadIdx.x;
    float s = bout[o];
    const float* wr = Wout + (size_t)o * D_;
    const float* pb = g_pb + b * D_;
    #pragma unroll 8
    for (int j = 0; j < D_; j++) s += pb[j] * wr[j];
    g_bias[b * D_ + o] = s;
}

// =====================================================================
// K5 (THE ONLY CHANGE): out = x @ E_b + bias via WMMA bf16 3-term split.
// fp32 -> bf16 hi/lo conversion happens inline while staging to smem.
// grid (64 t-tiles, 4 o-tiles, 4 b), block 256 (8 warps, warp tile 32x64).
// =====================================================================
#define TILE_BYTES_ (128 * LDS_ * 2)                 // 12288
#define TOFF_(t4) ((uint32_t)(t4) * TILE_BYTES_)     // 0=Ah,1=Al,2=Bh,3=Bl
#define K5_SMEM_ (128 * 132 * 4)                     // 67584 (epilogue high-water)

typedef wmma::fragment<wmma::matrix_a, 16, 16, 16, __nv_bfloat16, wmma::row_major> FragA;
typedef wmma::fragment<wmma::matrix_b, 16, 16, 16, __nv_bfloat16, wmma::col_major> FragB;
typedef wmma::fragment<wmma::accumulator, 16, 16, 16, float> FragC;

__global__ __launch_bounds__(256)
void k5_out(const float* __restrict__ x, float* __restrict__ out)
{
    extern __shared__ __align__(128) char smem[];
    const int tid = threadIdx.x, wid = tid >> 5;
    const int t0 = blockIdx.x * TT_, o0 = blockIdx.y * 128, b = blockIdx.z;
    const float* xb = x + (size_t)(b * T_ + t0) * D_;
    const float* Eb = g_E + (size_t)b * (D_ * D_);

    __nv_bfloat16* Ah = reinterpret_cast<__nv_bfloat16*>(smem + TOFF_(0));
    __nv_bfloat16* Al = reinterpret_cast<__nv_bfloat16*>(smem + TOFF_(1));
    __nv_bfloat16* Bh = reinterpret_cast<__nv_bfloat16*>(smem + TOFF_(2));
    __nv_bfloat16* Bl = reinterpret_cast<__nv_bfloat16*>(smem + TOFF_(3));

    const int m0 = (wid >> 1) * 32;
    const int n0 = (wid & 1) * 64;

    FragC acc[2][4];
    #pragma unroll
    for (int mt = 0; mt < 2; mt++)
        #pragma unroll
        for (int nt = 0; nt < 4; nt++) wmma::fill_fragment(acc[mt][nt], 0.f);

    for (int c = 0; c < NCH_; c++) {
        const int k0 = c * KC_;
        __syncthreads();
        // stage x [128 t][32 i] as bf16 hi/lo (vectorized fp32 loads)
        #pragma unroll
        for (int q = 0; q < 4; q++) {
            int flat = q * 256 + tid;          // 0..1023 float4s
            int r = flat >> 3, j = flat & 7;   // row, 4-float group
            float4 v = *reinterpret_cast<const float4*>(xb + (size_t)r * D_ + k0 + j * 4);
            __nv_bfloat162 h0 = __floats2bfloat162_rn(v.x, v.y);
            __nv_bfloat162 h1 = __floats2bfloat162_rn(v.z, v.w);
            __nv_bfloat162 l0 = __floats2bfloat162_rn(v.x - __low2float(h0), v.y - __high2float(h0));
            __nv_bfloat162 l1 = __floats2bfloat162_rn(v.z - __low2float(h1), v.w - __high2float(h1));
            int e = r * LDS_ + j * 4;
            *reinterpret_cast<__nv_bfloat162*>(Ah + e)     = h0;
            *reinterpret_cast<__nv_bfloat162*>(Ah + e + 2) = h1;
            *reinterpret_cast<__nv_bfloat162*>(Al + e)     = l0;
            *reinterpret_cast<__nv_bfloat162*>(Al + e + 2) = l1;
        }
        // stage E [32 i][128 o] -> col-major tiles [o][i] as bf16 hi/lo
        // (coalesced fp32 reads along o; scalar bf16 smem stores)
        #pragma unroll
        for (int q = 0; q < 16; q++) {
            int flat = q * 256 + tid;          // 0..4095
            int o = flat & 127, ii = flat >> 7;
            float e = Eb[(size_t)(k0 + ii) * D_ + o0 + o];
            __nv_bfloat16 hi = __float2bfloat16(e);
            Bh[o * LDS_ + ii] = hi;
            Bl[o * LDS_ + ii] = __float2bfloat16(e - __bfloat162float(hi));
        }
        __syncthreads();
        #pragma unroll
        for (int ks = 0; ks < KC_; ks += 16) {
            FragA fah[2], fal[2];
            FragB fbh[4], fbl[4];
            #pragma unroll
            for (int mt = 0; mt < 2; mt++) {
                wmma::load_matrix_sync(fah[mt], Ah + (m0 + mt * 16) * LDS_ + ks, LDS_);
                wmma::load_matrix_sync(fal[mt], Al + (m0 + mt * 16) * LDS_ + ks, LDS_);
            }
            #pragma unroll
            for (int nt = 0; nt < 4; nt++) {
                wmma::load_matrix_sync(fbh[nt], Bh + (n0 + nt * 16) * LDS_ + ks, LDS_);
                wmma::load_matrix_sync(fbl[nt], Bl + (n0 + nt * 16) * LDS_ + ks, LDS_);
            }
            #pragma unroll
            for (int mt = 0; mt < 2; mt++)
                #pragma unroll
                for (int nt = 0; nt < 4; nt++) {
                    wmma::mma_sync(acc[mt][nt], fah[mt], fbh[nt], acc[mt][nt]);
                    wmma::mma_sync(acc[mt][nt], fah[mt], fbl[nt], acc[mt][nt]);
                    wmma::mma_sync(acc[mt][nt], fal[mt], fbh[nt], acc[mt][nt]);
                }
        }
    }
    __syncthreads();

    // epilogue: acc -> smem stage -> +bias -> coalesced fp32 stores
    float* Stage = reinterpret_cast<float*>(smem);   // [128][132]
    #pragma unroll
    for (int mt = 0; mt < 2; mt++)
        #pragma unroll
        for (int nt = 0; nt < 4; nt++)
            wmma::store_matrix_sync(Stage + (m0 + mt * 16) * 132 + n0 + nt * 16,
                                    acc[mt][nt], 132, wmma::mem_row_major);
    __syncthreads();

    #pragma unroll
    for (int q = 0; q < 16; q++) {
        int flat = q * 256 + tid;          // 0..4095 float4s
        int r = flat >> 5, j = flat & 31;
        float4 v = *reinterpret_cast<const float4*>(Stage + r * 132 + j * 4);
        float4 bias = *reinterpret_cast<const float4*>(g_bias + b * D_ + o0 + j * 4);
        v.x += bias.x; v.y += bias.y; v.z += bias.z; v.w += bias.w;
        *reinterpret_cast<float4*>(out + (size_t)(b * T_ + t0 + r) * D_ + o0 + j * 4) = v;
    }
}

// =====================================================================
extern "C" void kernel_launch(void* const* d_in, const int* in_sizes, int n_in,
                              void* d_out, int out_size)
{
    (void)in_sizes; (void)n_in; (void)out_size;
    const float* x    = (const float*)d_in[0];
    const float* Wqkv = (const float*)d_in[1];
    const float* bqkv = (const float*)d_in[2];
    const float* Wout = (const float*)d_in[3];
    const float* bout = (const float*)d_in[4];
    float* out = (float*)d_out;

    const size_t K1_SMEM = 128 * 129 * sizeof(float); // 66048 B
    cudaFuncSetAttribute(k1_kv_context, cudaFuncAttributeMaxDynamicSharedMemorySize, (int)K1_SMEM);
    cudaFuncSetAttribute(k5_out, cudaFuncAttributeMaxDynamicSharedMemorySize, K5_SMEM_);

    k1_kv_context<<<dim3(NTILE_, H_, B_), 256, K1_SMEM>>>(x, Wqkv, bqkv);
    k2_reduce<<<B_ * H_, 256>>>();
    k3_A<<<B_ * H_, 256>>>(Wqkv);
    k3b_pb<<<B_, D_>>>(bqkv);
    k4_E<<<dim3(4, 4, B_), 256>>>(Wout);
    k4b_bias<<<B_, D_>>>(Wout, bout);
    k5_out<<<dim3(NTILE_, 4, B_), 256, K5_SMEM_>>>(x, out);
}

// round 10
// speedup vs baseline: 1.5527x; 1.4298x over previous
#include <cuda_runtime.h>
#include <cuda_bf16.h>
#include <mma.h>
#include <math.h>
#include <stdint.h>

using namespace nvcuda;

// LinearSelfAttention: B=4, T=8192, D=512, H=8, HD=64
// Round-9 PASS (1681us) with ONE change: k1_kv_context converted from SIMT
// to the SAME proven WMMA bf16 3-term-split pattern as k5_out (inline
// fp32->bf16 hi/lo staging). k5_out byte-identical to round 9.

#define B_ 4
#define T_ 8192
#define D_ 512
#define H_ 8
#define HD_ 64
#define TT_ 128            // token tile
#define NTILE_ (T_ / TT_)  // 64 tiles per batch
#define KC_ 32             // k-chunk for WMMA
#define NCH_ (D_ / KC_)    // 16
#define LDS_ 48            // smem row stride in bf16 (96B rows)

// ---------------- scratch (device globals; no allocs) ----------------
__device__ __align__(128) float g_Upart[B_ * NTILE_ * H_ * HD_ * HD_]; // 32 MB
__device__ __align__(128) float g_Spart[B_ * NTILE_ * H_ * HD_];
__device__ __align__(128) float g_C[B_ * H_ * HD_ * HD_];
__device__ __align__(128) float g_A[B_ * D_ * D_];
__device__ __align__(128) float g_E[B_ * D_ * D_];                     // [b][i][o]
__device__ __align__(128) float g_pb[B_ * D_];
__device__ __align__(128) float g_bias[B_ * D_];

#define TILE_BYTES_ (128 * LDS_ * 2)                 // 12288
#define TOFF_(t4) ((uint32_t)(t4) * TILE_BYTES_)     // 0=Ah,1=Al,2=Bh,3=Bl
#define WSMEM_ (128 * 132 * 4)                       // 67584 (epilogue high-water)

typedef wmma::fragment<wmma::matrix_a, 16, 16, 16, __nv_bfloat16, wmma::row_major> FragA;
typedef wmma::fragment<wmma::matrix_b, 16, 16, 16, __nv_bfloat16, wmma::col_major> FragB;
typedef wmma::fragment<wmma::accumulator, 16, 16, 16, float> FragC;

// =====================================================================
// K1 (THE ONLY CHANGE): WMMA split-bf16 KV projection + exp + U/S.
// grid (64 tiles, 8 heads, 4 b), block 256 (8 warps, warp tile 32x64).
// Computes [128 tok x 128 cols]: cols 0..63 = k_h, 64..127 = v_h.
// =====================================================================
__global__ __launch_bounds__(256)
void k1_kv_context(const float* __restrict__ x,
                   const float* __restrict__ Wqkv,
                   const float* __restrict__ bqkv)
{
    extern __shared__ __align__(128) char smem[];
    const int tid = threadIdx.x, wid = tid >> 5;
    const int tile = blockIdx.x, h = blockIdx.y, b = blockIdx.z;
    const float* xb = x + (size_t)(b * T_ + tile * TT_) * D_;
    const int wrow_k = D_ + h * HD_;       // k rows in W_qkv
    const int wrow_v = 2 * D_ + h * HD_;   // v rows

    __nv_bfloat16* Ah = reinterpret_cast<__nv_bfloat16*>(smem + TOFF_(0));
    __nv_bfloat16* Al = reinterpret_cast<__nv_bfloat16*>(smem + TOFF_(1));
    __nv_bfloat16* Bh = reinterpret_cast<__nv_bfloat16*>(smem + TOFF_(2));
    __nv_bfloat16* Bl = reinterpret_cast<__nv_bfloat16*>(smem + TOFF_(3));

    const int m0 = (wid >> 1) * 32;
    const int n0 = (wid & 1) * 64;

    FragC acc[2][4];
    #pragma unroll
    for (int mt = 0; mt < 2; mt++)
        #pragma unroll
        for (int nt = 0; nt < 4; nt++) wmma::fill_fragment(acc[mt][nt], 0.f);

    for (int c = 0; c < NCH_; c++) {
        const int k0 = c * KC_;
        __syncthreads();
        // stage x [128 t][32 i] as bf16 hi/lo (vectorized fp32 loads) — K5 pattern
        #pragma unroll
        for (int q = 0; q < 4; q++) {
            int flat = q * 256 + tid;          // 0..1023 float4s
            int r = flat >> 3, j = flat & 7;
            float4 v = *reinterpret_cast<const float4*>(xb + (size_t)r * D_ + k0 + j * 4);
            __nv_bfloat162 h0 = __floats2bfloat162_rn(v.x, v.y);
            __nv_bfloat162 h1 = __floats2bfloat162_rn(v.z, v.w);
            __nv_bfloat162 l0 = __floats2bfloat162_rn(v.x - __low2float(h0), v.y - __high2float(h0));
            __nv_bfloat162 l1 = __floats2bfloat162_rn(v.z - __low2float(h1), v.w - __high2float(h1));
            int e = r * LDS_ + j * 4;
            *reinterpret_cast<__nv_bfloat162*>(Ah + e)     = h0;
            *reinterpret_cast<__nv_bfloat162*>(Ah + e + 2) = h1;
            *reinterpret_cast<__nv_bfloat162*>(Al + e)     = l0;
            *reinterpret_cast<__nv_bfloat162*>(Al + e + 2) = l1;
        }
        // stage W [128 cols][32 k] as bf16 hi/lo; col<64 -> k rows, else v rows.
        // reads coalesce along k within a row; smem stores at consecutive bf16 addrs.
        #pragma unroll
        for (int q = 0; q < 16; q++) {
            int flat = q * 256 + tid;          // 0..4095
            int kk = flat & 31, col = flat >> 5;
            int wrow = (col < 64) ? (wrow_k + col) : (wrow_v + col - 64);
            float w = Wqkv[(size_t)wrow * D_ + k0 + kk];
            __nv_bfloat16 hi = __float2bfloat16(w);
            Bh[col * LDS_ + kk] = hi;
            Bl[col * LDS_ + kk] = __float2bfloat16(w - __bfloat162float(hi));
        }
        __syncthreads();
        #pragma unroll
        for (int ks = 0; ks < KC_; ks += 16) {
            FragA fah[2], fal[2];
            FragB fbh[4], fbl[4];
            #pragma unroll
            for (int mt = 0; mt < 2; mt++) {
                wmma::load_matrix_sync(fah[mt], Ah + (m0 + mt * 16) * LDS_ + ks, LDS_);
                wmma::load_matrix_sync(fal[mt], Al + (m0 + mt * 16) * LDS_ + ks, LDS_);
            }
            #pragma unroll
            for (int nt = 0; nt < 4; nt++) {
                wmma::load_matrix_sync(fbh[nt], Bh + (n0 + nt * 16) * LDS_ + ks, LDS_);
                wmma::load_matrix_sync(fbl[nt], Bl + (n0 + nt * 16) * LDS_ + ks, LDS_);
            }
            #pragma unroll
            for (int mt = 0; mt < 2; mt++)
                #pragma unroll
                for (int nt = 0; nt < 4; nt++) {
                    wmma::mma_sync(acc[mt][nt], fah[mt], fbh[nt], acc[mt][nt]);
                    wmma::mma_sync(acc[mt][nt], fah[mt], fbl[nt], acc[mt][nt]);
                    wmma::mma_sync(acc[mt][nt], fal[mt], fbh[nt], acc[mt][nt]);
                }
        }
    }
    __syncthreads();

    // epilogue: acc -> KV smem [128][132] fp32
    float* KV = reinterpret_cast<float*>(smem);
    #pragma unroll
    for (int mt = 0; mt < 2; mt++)
        #pragma unroll
        for (int nt = 0; nt < 4; nt++)
            wmma::store_matrix_sync(KV + (m0 + mt * 16) * 132 + n0 + nt * 16,
                                    acc[mt][nt], 132, wmma::mem_row_major);
    __syncthreads();

    // bias + exp on k-half
    #pragma unroll
    for (int i = 0; i < 64; i++) {
        int flat = i * 256 + tid;          // 0..16383
        int r = flat >> 7, cc = flat & 127;
        float v = KV[r * 132 + cc];
        if (cc < 64) v = expf(v + bqkv[wrow_k + cc]);
        else         v = v + bqkv[wrow_v + cc - 64];
        KV[r * 132 + cc] = v;
    }
    __syncthreads();

    // U = EK^T @ V (16x16 threads, 4x4 micro)
    const int tx = tid & 15, ty = tid >> 4;
    float u[4][4];
    #pragma unroll
    for (int dd = 0; dd < 4; dd++)
        #pragma unroll
        for (int vv = 0; vv < 4; vv++) u[dd][vv] = 0.f;
    for (int t = 0; t < TT_; t++) {
        float a_[4], b_[4];
        #pragma unroll
        for (int dd = 0; dd < 4; dd++) a_[dd] = KV[t * 132 + ty * 4 + dd];
        #pragma unroll
        for (int vv = 0; vv < 4; vv++) b_[vv] = KV[t * 132 + 64 + tx * 4 + vv];
        #pragma unroll
        for (int dd = 0; dd < 4; dd++)
            #pragma unroll
            for (int vv = 0; vv < 4; vv++) u[dd][vv] += a_[dd] * b_[vv];
    }
    size_t ubase = (size_t)((b * NTILE_ + tile) * H_ + h) * (HD_ * HD_);
    #pragma unroll
    for (int dd = 0; dd < 4; dd++)
        #pragma unroll
        for (int vv = 0; vv < 4; vv++)
            g_Upart[ubase + (ty * 4 + dd) * HD_ + tx * 4 + vv] = u[dd][vv];
    if (tid < 64) {
        float ssum = 0.f;
        for (int t = 0; t < TT_; t++) ssum += KV[t * 132 + tid];
        g_Spart[((b * NTILE_ + tile) * H_ + h) * HD_ + tid] = ssum;
    }
}

// =====================================================================
// K2: reduce partials -> C = U / S  (round-1 verbatim)
// =====================================================================
__global__ void k2_reduce()
{
    const int b = blockIdx.x >> 3, h = blockIdx.x & 7;
    const int tid = threadIdx.x;
    __shared__ float S[64];
    if (tid < 64) {
        float s = 0.f;
        for (int t = 0; t < NTILE_; t++)
            s += g_Spart[((b * NTILE_ + t) * H_ + h) * HD_ + tid];
        S[tid] = s;
    }
    __syncthreads();
    for (int e = tid; e < HD_ * HD_; e += 256) {
        float u = 0.f;
        #pragma unroll 8
        for (int t = 0; t < NTILE_; t++)
            u += g_Upart[(size_t)((b * NTILE_ + t) * H_ + h) * (HD_ * HD_) + e];
        g_C[(b * H_ + h) * (HD_ * HD_) + e] = u / S[e >> 6];
    }
}

// =====================================================================
// K3: A[b][j][i]  (round-1 verbatim)
// =====================================================================
__global__ void k3_A(const float* __restrict__ Wqkv)
{
    const int b = blockIdx.x >> 3, h = blockIdx.x & 7;
    const int tid = threadIdx.x;
    __shared__ float Ch[64 * 64];
    __shared__ float Wc[64 * 128];
    for (int e = tid; e < 4096; e += 256)
        Ch[e] = g_C[(b * H_ + h) * 4096 + e];
    for (int chunk = 0; chunk < 4; chunk++) {
        int i0 = chunk * 128;
        __syncthreads();
        for (int e = tid; e < 64 * 128; e += 256) {
            int d = e >> 7, ii = e & 127;
            Wc[e] = Wqkv[(size_t)(h * HD_ + d) * D_ + i0 + ii];
        }
        __syncthreads();
        for (int idx = tid; idx < 64 * 128; idx += 256) {
            int vv = idx >> 7, ii = idx & 127;
            float s = 0.f;
            #pragma unroll
            for (int d = 0; d < 64; d++) s += Ch[d * 64 + vv] * Wc[d * 128 + ii];
            g_A[(size_t)b * (D_ * D_) + (size_t)(h * HD_ + vv) * D_ + i0 + ii] = s;
        }
    }
}

__global__ void k3b_pb(const float* __restrict__ bqkv)
{
    const int b = blockIdx.x;
    const int j = threadIdx.x;
    const int h = j >> 6, vv = j & 63;
    float s = 0.f;
    for (int d = 0; d < 64; d++)
        s += bqkv[h * HD_ + d] * g_C[(b * H_ + h) * 4096 + d * 64 + vv];
    g_pb[b * D_ + j] = s;
}

// =====================================================================
// K4: E[b][i][o]  (round-1 verbatim, fp32)
// =====================================================================
__global__ __launch_bounds__(256, 2)
void k4_E(const float* __restrict__ Wout)
{
    const int tid = threadIdx.x;
    const int tx = tid & 15, ty = tid >> 4;
    const int i0 = blockIdx.x * 128, o0 = blockIdx.y * 128, b = blockIdx.z;
    __shared__ float Xs[128 * 17];
    __shared__ float Ws[128 * 17];
    const float* Ab = g_A + (size_t)b * (D_ * D_);

    float acc[8][8];
    #pragma unroll
    for (int r = 0; r < 8; r++)
        #pragma unroll
        for (int c = 0; c < 8; c++) acc[r][c] = 0.f;

    for (int j0 = 0; j0 < D_; j0 += 16) {
        #pragma unroll
        for (int q = 0; q < 2; q++) {
            int flat = tid * 2 + q;
            int jj = flat >> 5;
            int ii = (flat & 31) * 4;
            float4 t = *reinterpret_cast<const float4*>(Ab + (size_t)(j0 + jj) * D_ + i0 + ii);
            Xs[(ii + 0) * 17 + jj] = t.x;
            Xs[(ii + 1) * 17 + jj] = t.y;
            Xs[(ii + 2) * 17 + jj] = t.z;
            Xs[(ii + 3) * 17 + jj] = t.w;
        }
        #pragma unroll
        for (int q = 0; q < 2; q++) {
            int flat = tid * 2 + q;
            int col = flat >> 2;
            int c4 = (flat & 3) * 4;
            float4 t = *reinterpret_cast<const float4*>(Wout + (size_t)(o0 + col) * D_ + j0 + c4);
            float* dst = Ws + col * 17 + c4;
            dst[0] = t.x; dst[1] = t.y; dst[2] = t.z; dst[3] = t.w;
        }
        __syncthreads();
        #pragma unroll
        for (int kk = 0; kk < 16; kk++) {
            float a_[8], b_[8];
            #pragma unroll
            for (int r = 0; r < 8; r++) a_[r] = Xs[(ty * 8 + r) * 17 + kk];
            #pragma unroll
            for (int c = 0; c < 8; c++) b_[c] = Ws[(tx + 16 * c) * 17 + kk];
            #pragma unroll
            for (int r = 0; r < 8; r++)
                #pragma unroll
                for (int c = 0; c < 8; c++) acc[r][c] += a_[r] * b_[c];
        }
        __syncthreads();
    }
    #pragma unroll
    for (int r = 0; r < 8; r++)
        #pragma unroll
        for (int c = 0; c < 8; c++)
            g_E[(size_t)b * (D_ * D_) + (size_t)(i0 + ty * 8 + r) * D_ + o0 + tx + 16 * c] = acc[r][c];
}

__global__ void k4b_bias(const float* __restrict__ Wout, const float* __restrict__ bout)
{
    const int b = blockIdx.x;
    const int o = threadIdx.x;
    float s = bout[o];
    const float* wr = Wout + (size_t)o * D_;
    const float* pb = g_pb + b * D_;
    #pragma unroll 8
    for (int j = 0; j < D_; j++) s += pb[j] * wr[j];
    g_bias[b * D_ + o] = s;
}

// =====================================================================
// K5: out = x @ E_b + bias via WMMA bf16 3-term split. (round-9 verbatim)
// =====================================================================
__global__ __launch_bounds__(256)
void k5_out(const float* __restrict__ x, float* __restrict__ out)
{
    extern __shared__ __align__(128) char smem[];
    const int tid = threadIdx.x, wid = tid >> 5;
    const int t0 = blockIdx.x * TT_, o0 = blockIdx.y * 128, b = blockIdx.z;
    const float* xb = x + (size_t)(b * T_ + t0) * D_;
    const float* Eb = g_E + (size_t)b * (D_ * D_);

    __nv_bfloat16* Ah = reinterpret_cast<__nv_bfloat16*>(smem + TOFF_(0));
    __nv_bfloat16* Al = reinterpret_cast<__nv_bfloat16*>(smem + TOFF_(1));
    __nv_bfloat16* Bh = reinterpret_cast<__nv_bfloat16*>(smem + TOFF_(2));
    __nv_bfloat16* Bl = reinterpret_cast<__nv_bfloat16*>(smem + TOFF_(3));

    const int m0 = (wid >> 1) * 32;
    const int n0 = (wid & 1) * 64;

    FragC acc[2][4];
    #pragma unroll
    for (int mt = 0; mt < 2; mt++)
        #pragma unroll
        for (int nt = 0; nt < 4; nt++) wmma::fill_fragment(acc[mt][nt], 0.f);

    for (int c = 0; c < NCH_; c++) {
        const int k0 = c * KC_;
        __syncthreads();
        #pragma unroll
        for (int q = 0; q < 4; q++) {
            int flat = q * 256 + tid;
            int r = flat >> 3, j = flat & 7;
            float4 v = *reinterpret_cast<const float4*>(xb + (size_t)r * D_ + k0 + j * 4);
            __nv_bfloat162 h0 = __floats2bfloat162_rn(v.x, v.y);
            __nv_bfloat162 h1 = __floats2bfloat162_rn(v.z, v.w);
            __nv_bfloat162 l0 = __floats2bfloat162_rn(v.x - __low2float(h0), v.y - __high2float(h0));
            __nv_bfloat162 l1 = __floats2bfloat162_rn(v.z - __low2float(h1), v.w - __high2float(h1));
            int e = r * LDS_ + j * 4;
            *reinterpret_cast<__nv_bfloat162*>(Ah + e)     = h0;
            *reinterpret_cast<__nv_bfloat162*>(Ah + e + 2) = h1;
            *reinterpret_cast<__nv_bfloat162*>(Al + e)     = l0;
            *reinterpret_cast<__nv_bfloat162*>(Al + e + 2) = l1;
        }
        #pragma unroll
        for (int q = 0; q < 16; q++) {
            int flat = q * 256 + tid;
            int o = flat & 127, ii = flat >> 7;
            float e = Eb[(size_t)(k0 + ii) * D_ + o0 + o];
            __nv_bfloat16 hi = __float2bfloat16(e);
            Bh[o * LDS_ + ii] = hi;
            Bl[o * LDS_ + ii] = __float2bfloat16(e - __bfloat162float(hi));
        }
        __syncthreads();
        #pragma unroll
        for (int ks = 0; ks < KC_; ks += 16) {
            FragA fah[2], fal[2];
            FragB fbh[4], fbl[4];
            #pragma unroll
            for (int mt = 0; mt < 2; mt++) {
                wmma::load_matrix_sync(fah[mt], Ah + (m0 + mt * 16) * LDS_ + ks, LDS_);
                wmma::load_matrix_sync(fal[mt], Al + (m0 + mt * 16) * LDS_ + ks, LDS_);
            }
            #pragma unroll
            for (int nt = 0; nt < 4; nt++) {
                wmma::load_matrix_sync(fbh[nt], Bh + (n0 + nt * 16) * LDS_ + ks, LDS_);
                wmma::load_matrix_sync(fbl[nt], Bl + (n0 + nt * 16) * LDS_ + ks, LDS_);
            }
            #pragma unroll
            for (int mt = 0; mt < 2; mt++)
                #pragma unroll
                for (int nt = 0; nt < 4; nt++) {
                    wmma::mma_sync(acc[mt][nt], fah[mt], fbh[nt], acc[mt][nt]);
                    wmma::mma_sync(acc[mt][nt], fah[mt], fbl[nt], acc[mt][nt]);
                    wmma::mma_sync(acc[mt][nt], fal[mt], fbh[nt], acc[mt][nt]);
                }
        }
    }
    __syncthreads();

    float* Stage = reinterpret_cast<float*>(smem);   // [128][132]
    #pragma unroll
    for (int mt = 0; mt < 2; mt++)
        #pragma unroll
        for (int nt = 0; nt < 4; nt++)
            wmma::store_matrix_sync(Stage + (m0 + mt * 16) * 132 + n0 + nt * 16,
                                    acc[mt][nt], 132, wmma::mem_row_major);
    __syncthreads();

    #pragma unroll
    for (int q = 0; q < 16; q++) {
        int flat = q * 256 + tid;
        int r = flat >> 5, j = flat & 31;
        float4 v = *reinterpret_cast<const float4*>(Stage + r * 132 + j * 4);
        float4 bias = *reinterpret_cast<const float4*>(g_bias + b * D_ + o0 + j * 4);
        v.x += bias.x; v.y += bias.y; v.z += bias.z; v.w += bias.w;
        *reinterpret_cast<float4*>(out + (size_t)(b * T_ + t0 + r) * D_ + o0 + j * 4) = v;
    }
}

// =====================================================================
extern "C" void kernel_launch(void* const* d_in, const int* in_sizes, int n_in,
                              void* d_out, int out_size)
{
    (void)in_sizes; (void)n_in; (void)out_size;
    const float* x    = (const float*)d_in[0];
    const float* Wqkv = (const float*)d_in[1];
    const float* bqkv = (const float*)d_in[2];
    const float* Wout = (const float*)d_in[3];
    const float* bout = (const float*)d_in[4];
    float* out = (float*)d_out;

    cudaFuncSetAttribute(k1_kv_context, cudaFuncAttributeMaxDynamicSharedMemorySize, WSMEM_);
    cudaFuncSetAttribute(k5_out, cudaFuncAttributeMaxDynamicSharedMemorySize, WSMEM_);

    k1_kv_context<<<dim3(NTILE_, H_, B_), 256, WSMEM_>>>(x, Wqkv, bqkv);
    k2_reduce<<<B_ * H_, 256>>>();
    k3_A<<<B_ * H_, 256>>>(Wqkv);
    k3b_pb<<<B_, D_>>>(bqkv);
    k4_E<<<dim3(4, 4, B_), 256>>>(Wout);
    k4b_bias<<<B_, D_>>>(Wout, bout);
    k5_out<<<dim3(NTILE_, 4, B_), 256, WSMEM_>>>(x, out);
}

// round 11
// speedup vs baseline: 1.7725x; 1.1416x over previous
#include <cuda_runtime.h>
#include <cuda_bf16.h>
#include <mma.h>
#include <math.h>
#include <stdint.h>

using namespace nvcuda;

// LinearSelfAttention: B=4, T=8192, D=512, H=8, HD=64
// Round-10 PASS (1176us) + staging optimizations:
//  - K1/K5: double-buffered smem staging (overlap global loads with MMA)
//  - K1: vectorized W staging (float4)
//  - K4: writes E^T [b][o][i] fp32; K5 stages E via float4 rows (no transpose-on-stage)

#define B_ 4
#define T_ 8192
#define D_ 512
#define H_ 8
#define HD_ 64
#define TT_ 128            // token tile
#define NTILE_ (T_ / TT_)  // 64
#define KC_ 32             // k-chunk
#define NCH_ (D_ / KC_)    // 16
#define LDS_ 48            // smem row stride in bf16 (96B rows)

// ---------------- scratch (device globals; no allocs) ----------------
__device__ __align__(128) float g_Upart[B_ * NTILE_ * H_ * HD_ * HD_]; // 32 MB
__device__ __align__(128) float g_Spart[B_ * NTILE_ * H_ * HD_];
__device__ __align__(128) float g_C[B_ * H_ * HD_ * HD_];
__device__ __align__(128) float g_A[B_ * D_ * D_];
__device__ __align__(128) float g_Et[B_ * D_ * D_];                    // E^T [b][o][i]
__device__ __align__(128) float g_pb[B_ * D_];
__device__ __align__(128) float g_bias[B_ * D_];

#define TILE_BYTES_ (128 * LDS_ * 2)                       // 12288
#define BTOFF_(s, t4) ((uint32_t)(s) * (4 * TILE_BYTES_) + (uint32_t)(t4) * TILE_BYTES_)
#define WSMEM_ (2 * 4 * TILE_BYTES_)                       // 98304

typedef wmma::fragment<wmma::matrix_a, 16, 16, 16, __nv_bfloat16, wmma::row_major> FragA;
typedef wmma::fragment<wmma::matrix_b, 16, 16, 16, __nv_bfloat16, wmma::col_major> FragB;
typedef wmma::fragment<wmma::accumulator, 16, 16, 16, float> FragC;

// convert float4 -> bf16 hi/lo pairs and store 8B each
__device__ __forceinline__ void split_store(__nv_bfloat16* Hi, __nv_bfloat16* Lo,
                                            int e, float4 v)
{
    __nv_bfloat162 h0 = __floats2bfloat162_rn(v.x, v.y);
    __nv_bfloat162 h1 = __floats2bfloat162_rn(v.z, v.w);
    __nv_bfloat162 l0 = __floats2bfloat162_rn(v.x - __low2float(h0), v.y - __high2float(h0));
    __nv_bfloat162 l1 = __floats2bfloat162_rn(v.z - __low2float(h1), v.w - __high2float(h1));
    *reinterpret_cast<__nv_bfloat162*>(Hi + e)     = h0;
    *reinterpret_cast<__nv_bfloat162*>(Hi + e + 2) = h1;
    *reinterpret_cast<__nv_bfloat162*>(Lo + e)     = l0;
    *reinterpret_cast<__nv_bfloat162*>(Lo + e + 2) = l1;
}

// =====================================================================
// K1: WMMA split-bf16 KV projection + exp + U/S. Double-buffered staging.
// grid (64 tiles, 8 heads, 4 b), block 256 (8 warps, warp tile 32x64).
// =====================================================================
__global__ __launch_bounds__(256)
void k1_kv_context(const float* __restrict__ x,
                   const float* __restrict__ Wqkv,
                   const float* __restrict__ bqkv)
{
    extern __shared__ __align__(128) char smem[];
    const int tid = threadIdx.x, wid = tid >> 5;
    const int tile = blockIdx.x, h = blockIdx.y, b = blockIdx.z;
    const float* xb = x + (size_t)(b * T_ + tile * TT_) * D_;
    const int wrow_k = D_ + h * HD_;
    const int wrow_v = 2 * D_ + h * HD_;

    const int m0 = (wid >> 1) * 32;
    const int n0 = (wid & 1) * 64;

    FragC acc[2][4];
    #pragma unroll
    for (int mt = 0; mt < 2; mt++)
        #pragma unroll
        for (int nt = 0; nt < 4; nt++) wmma::fill_fragment(acc[mt][nt], 0.f);

    auto stage = [&](int c, int s) {
        const int k0 = c * KC_;
        __nv_bfloat16* Ah = reinterpret_cast<__nv_bfloat16*>(smem + BTOFF_(s, 0));
        __nv_bfloat16* Al = reinterpret_cast<__nv_bfloat16*>(smem + BTOFF_(s, 1));
        __nv_bfloat16* Bh = reinterpret_cast<__nv_bfloat16*>(smem + BTOFF_(s, 2));
        __nv_bfloat16* Bl = reinterpret_cast<__nv_bfloat16*>(smem + BTOFF_(s, 3));
        #pragma unroll
        for (int q = 0; q < 4; q++) {           // x: [128 t][32 i]
            int flat = q * 256 + tid;           // 0..1023 float4s
            int r = flat >> 3, j = flat & 7;
            float4 v = *reinterpret_cast<const float4*>(xb + (size_t)r * D_ + k0 + j * 4);
            split_store(Ah, Al, r * LDS_ + j * 4, v);
        }
        #pragma unroll
        for (int q = 0; q < 4; q++) {           // W: [128 cols][32 k]
            int flat = q * 256 + tid;
            int col = flat >> 3, j = flat & 7;
            int wrow = (col < 64) ? (wrow_k + col) : (wrow_v + col - 64);
            float4 w = *reinterpret_cast<const float4*>(Wqkv + (size_t)wrow * D_ + k0 + j * 4);
            split_store(Bh, Bl, col * LDS_ + j * 4, w);
        }
    };

    stage(0, 0);
    __syncthreads();

    for (int c = 0; c < NCH_; c++) {
        const int s = c & 1;
        if (c + 1 < NCH_) stage(c + 1, s ^ 1);   // overlaps with MMA below
        const __nv_bfloat16* Ah = reinterpret_cast<const __nv_bfloat16*>(smem + BTOFF_(s, 0));
        const __nv_bfloat16* Al = reinterpret_cast<const __nv_bfloat16*>(smem + BTOFF_(s, 1));
        const __nv_bfloat16* Bh = reinterpret_cast<const __nv_bfloat16*>(smem + BTOFF_(s, 2));
        const __nv_bfloat16* Bl = reinterpret_cast<const __nv_bfloat16*>(smem + BTOFF_(s, 3));
        #pragma unroll
        for (int ks = 0; ks < KC_; ks += 16) {
            FragA fah[2], fal[2];
            FragB fbh[4], fbl[4];
            #pragma unroll
            for (int mt = 0; mt < 2; mt++) {
                wmma::load_matrix_sync(fah[mt], Ah + (m0 + mt * 16) * LDS_ + ks, LDS_);
                wmma::load_matrix_sync(fal[mt], Al + (m0 + mt * 16) * LDS_ + ks, LDS_);
            }
            #pragma unroll
            for (int nt = 0; nt < 4; nt++) {
                wmma::load_matrix_sync(fbh[nt], Bh + (n0 + nt * 16) * LDS_ + ks, LDS_);
                wmma::load_matrix_sync(fbl[nt], Bl + (n0 + nt * 16) * LDS_ + ks, LDS_);
            }
            #pragma unroll
            for (int mt = 0; mt < 2; mt++)
                #pragma unroll
                for (int nt = 0; nt < 4; nt++) {
                    wmma::mma_sync(acc[mt][nt], fah[mt], fbh[nt], acc[mt][nt]);
                    wmma::mma_sync(acc[mt][nt], fah[mt], fbl[nt], acc[mt][nt]);
                    wmma::mma_sync(acc[mt][nt], fal[mt], fbh[nt], acc[mt][nt]);
                }
        }
        __syncthreads();   // MMA on buf s done; stores to buf s^1 complete
    }

    // epilogue: acc -> KV smem [128][132] fp32
    float* KV = reinterpret_cast<float*>(smem);
    #pragma unroll
    for (int mt = 0; mt < 2; mt++)
        #pragma unroll
        for (int nt = 0; nt < 4; nt++)
            wmma::store_matrix_sync(KV + (m0 + mt * 16) * 132 + n0 + nt * 16,
                                    acc[mt][nt], 132, wmma::mem_row_major);
    __syncthreads();

    // bias + exp on k-half
    #pragma unroll
    for (int i = 0; i < 64; i++) {
        int flat = i * 256 + tid;
        int r = flat >> 7, cc = flat & 127;
        float v = KV[r * 132 + cc];
        if (cc < 64) v = expf(v + bqkv[wrow_k + cc]);
        else         v = v + bqkv[wrow_v + cc - 64];
        KV[r * 132 + cc] = v;
    }
    __syncthreads();

    // U = EK^T @ V (16x16 threads, 4x4 micro)
    const int tx = tid & 15, ty = tid >> 4;
    float u[4][4];
    #pragma unroll
    for (int dd = 0; dd < 4; dd++)
        #pragma unroll
        for (int vv = 0; vv < 4; vv++) u[dd][vv] = 0.f;
    for (int t = 0; t < TT_; t++) {
        float a_[4], b_[4];
        #pragma unroll
        for (int dd = 0; dd < 4; dd++) a_[dd] = KV[t * 132 + ty * 4 + dd];
        #pragma unroll
        for (int vv = 0; vv < 4; vv++) b_[vv] = KV[t * 132 + 64 + tx * 4 + vv];
        #pragma unroll
        for (int dd = 0; dd < 4; dd++)
            #pragma unroll
            for (int vv = 0; vv < 4; vv++) u[dd][vv] += a_[dd] * b_[vv];
    }
    size_t ubase = (size_t)((b * NTILE_ + tile) * H_ + h) * (HD_ * HD_);
    #pragma unroll
    for (int dd = 0; dd < 4; dd++)
        #pragma unroll
        for (int vv = 0; vv < 4; vv++)
            g_Upart[ubase + (ty * 4 + dd) * HD_ + tx * 4 + vv] = u[dd][vv];
    if (tid < 64) {
        float ssum = 0.f;
        for (int t = 0; t < TT_; t++) ssum += KV[t * 132 + tid];
        g_Spart[((b * NTILE_ + tile) * H_ + h) * HD_ + tid] = ssum;
    }
}

// =====================================================================
// K2: reduce partials -> C = U / S  (unchanged)
// =====================================================================
__global__ void k2_reduce()
{
    const int b = blockIdx.x >> 3, h = blockIdx.x & 7;
    const int tid = threadIdx.x;
    __shared__ float S[64];
    if (tid < 64) {
        float s = 0.f;
        for (int t = 0; t < NTILE_; t++)
            s += g_Spart[((b * NTILE_ + t) * H_ + h) * HD_ + tid];
        S[tid] = s;
    }
    __syncthreads();
    for (int e = tid; e < HD_ * HD_; e += 256) {
        float u = 0.f;
        #pragma unroll 8
        for (int t = 0; t < NTILE_; t++)
            u += g_Upart[(size_t)((b * NTILE_ + t) * H_ + h) * (HD_ * HD_) + e];
        g_C[(b * H_ + h) * (HD_ * HD_) + e] = u / S[e >> 6];
    }
}

// =====================================================================
// K3: A[b][j][i]  (unchanged)
// =====================================================================
__global__ void k3_A(const float* __restrict__ Wqkv)
{
    const int b = blockIdx.x >> 3, h = blockIdx.x & 7;
    const int tid = threadIdx.x;
    __shared__ float Ch[64 * 64];
    __shared__ float Wc[64 * 128];
    for (int e = tid; e < 4096; e += 256)
        Ch[e] = g_C[(b * H_ + h) * 4096 + e];
    for (int chunk = 0; chunk < 4; chunk++) {
        int i0 = chunk * 128;
        __syncthreads();
        for (int e = tid; e < 64 * 128; e += 256) {
            int d = e >> 7, ii = e & 127;
            Wc[e] = Wqkv[(size_t)(h * HD_ + d) * D_ + i0 + ii];
        }
        __syncthreads();
        for (int idx = tid; idx < 64 * 128; idx += 256) {
            int vv = idx >> 7, ii = idx & 127;
            float s = 0.f;
            #pragma unroll
            for (int d = 0; d < 64; d++) s += Ch[d * 64 + vv] * Wc[d * 128 + ii];
            g_A[(size_t)b * (D_ * D_) + (size_t)(h * HD_ + vv) * D_ + i0 + ii] = s;
        }
    }
}

__global__ void k3b_pb(const float* __restrict__ bqkv)
{
    const int b = blockIdx.x;
    const int j = threadIdx.x;
    const int h = j >> 6, vv = j & 63;
    float s = 0.f;
    for (int d = 0; d < 64; d++)
        s += bqkv[h * HD_ + d] * g_C[(b * H_ + h) * 4096 + d * 64 + vv];
    g_pb[b * D_ + j] = s;
}

// =====================================================================
// K4: E computed as before but stored TRANSPOSED: g_Et[b][o][i].
// Per-thread float4 stores along i (i = i0 + ty*8 + 0..7).
// =====================================================================
__global__ __launch_bounds__(256, 2)
void k4_E(const float* __restrict__ Wout)
{
    const int tid = threadIdx.x;
    const int tx = tid & 15, ty = tid >> 4;
    const int i0 = blockIdx.x * 128, o0 = blockIdx.y * 128, b = blockIdx.z;
    __shared__ float Xs[128 * 17];
    __shared__ float Ws[128 * 17];
    const float* Ab = g_A + (size_t)b * (D_ * D_);

    float acc[8][8];
    #pragma unroll
    for (int r = 0; r < 8; r++)
        #pragma unroll
        for (int c = 0; c < 8; c++) acc[r][c] = 0.f;

    for (int j0 = 0; j0 < D_; j0 += 16) {
        #pragma unroll
        for (int q = 0; q < 2; q++) {
            int flat = tid * 2 + q;
            int jj = flat >> 5;
            int ii = (flat & 31) * 4;
            float4 t = *reinterpret_cast<const float4*>(Ab + (size_t)(j0 + jj) * D_ + i0 + ii);
            Xs[(ii + 0) * 17 + jj] = t.x;
            Xs[(ii + 1) * 17 + jj] = t.y;
            Xs[(ii + 2) * 17 + jj] = t.z;
            Xs[(ii + 3) * 17 + jj] = t.w;
        }
        #pragma unroll
        for (int q = 0; q < 2; q++) {
            int flat = tid * 2 + q;
            int col = flat >> 2;
            int c4 = (flat & 3) * 4;
            float4 t = *reinterpret_cast<const float4*>(Wout + (size_t)(o0 + col) * D_ + j0 + c4);
            float* dst = Ws + col * 17 + c4;
            dst[0] = t.x; dst[1] = t.y; dst[2] = t.z; dst[3] = t.w;
        }
        __syncthreads();
        #pragma unroll
        for (int kk = 0; kk < 16; kk++) {
            float a_[8], b_[8];
            #pragma unroll
            for (int r = 0; r < 8; r++) a_[r] = Xs[(ty * 8 + r) * 17 + kk];
            #pragma unroll
            for (int c = 0; c < 8; c++) b_[c] = Ws[(tx + 16 * c) * 17 + kk];
            #pragma unroll
            for (int r = 0; r < 8; r++)
                #pragma unroll
                for (int c = 0; c < 8; c++) acc[r][c] += a_[r] * b_[c];
        }
        __syncthreads();
    }
    // E^T store: row o, 8 consecutive i per thread (two float4s)
    float* Eb = g_Et + (size_t)b * (D_ * D_);
    #pragma unroll
    for (int c = 0; c < 8; c++) {
        int o = o0 + tx + 16 * c;
        float4 v0 = make_float4(acc[0][c], acc[1][c], acc[2][c], acc[3][c]);
        float4 v1 = make_float4(acc[4][c], acc[5][c], acc[6][c], acc[7][c]);
        *reinterpret_cast<float4*>(Eb + (size_t)o * D_ + i0 + ty * 8)     = v0;
        *reinterpret_cast<float4*>(Eb + (size_t)o * D_ + i0 + ty * 8 + 4) = v1;
    }
}

__global__ void k4b_bias(const float* __restrict__ Wout, const float* __restrict__ bout)
{
    const int b = blockIdx.x;
    const int o = threadIdx.x;
    float s = bout[o];
    const float* wr = Wout + (size_t)o * D_;
    const float* pb = g_pb + b * D_;
    #pragma unroll 8
    for (int j = 0; j < D_; j++) s += pb[j] * wr[j];
    g_bias[b * D_ + o] = s;
}

// =====================================================================
// K5: out = x @ E_b + bias, WMMA split-bf16, double-buffered staging.
// E read from E^T rows (float4, no transpose-on-stage).
// =====================================================================
__global__ __launch_bounds__(256)
void k5_out(const float* __restrict__ x, float* __restrict__ out)
{
    extern __shared__ __align__(128) char smem[];
    const int tid = threadIdx.x, wid = tid >> 5;
    const int t0 = blockIdx.x * TT_, o0 = blockIdx.y * 128, b = blockIdx.z;
    const float* xb = x + (size_t)(b * T_ + t0) * D_;
    const float* Eb = g_Et + (size_t)b * (D_ * D_);

    const int m0 = (wid >> 1) * 32;
    const int n0 = (wid & 1) * 64;

    FragC acc[2][4];
    #pragma unroll
    for (int mt = 0; mt < 2; mt++)
        #pragma unroll
        for (int nt = 0; nt < 4; nt++) wmma::fill_fragment(acc[mt][nt], 0.f);

    auto stage = [&](int c, int s) {
        const int k0 = c * KC_;
        __nv_bfloat16* Ah = reinterpret_cast<__nv_bfloat16*>(smem + BTOFF_(s, 0));
        __nv_bfloat16* Al = reinterpret_cast<__nv_bfloat16*>(smem + BTOFF_(s, 1));
        __nv_bfloat16* Bh = reinterpret_cast<__nv_bfloat16*>(smem + BTOFF_(s, 2));
        __nv_bfloat16* Bl = reinterpret_cast<__nv_bfloat16*>(smem + BTOFF_(s, 3));
        #pragma unroll
        for (int q = 0; q < 4; q++) {           // x
            int flat = q * 256 + tid;
            int r = flat >> 3, j = flat & 7;
            float4 v = *reinterpret_cast<const float4*>(xb + (size_t)r * D_ + k0 + j * 4);
            split_store(Ah, Al, r * LDS_ + j * 4, v);
        }
        #pragma unroll
        for (int q = 0; q < 4; q++) {           // E^T rows: [128 o][32 i]
            int flat = q * 256 + tid;
            int o = flat >> 3, j = flat & 7;
            float4 v = *reinterpret_cast<const float4*>(Eb + (size_t)(o0 + o) * D_ + k0 + j * 4);
            split_store(Bh, Bl, o * LDS_ + j * 4, v);
        }
    };

    stage(0, 0);
    __syncthreads();

    for (int c = 0; c < NCH_; c++) {
        const int s = c & 1;
        if (c + 1 < NCH_) stage(c + 1, s ^ 1);
        const __nv_bfloat16* Ah = reinterpret_cast<const __nv_bfloat16*>(smem + BTOFF_(s, 0));
        const __nv_bfloat16* Al = reinterpret_cast<const __nv_bfloat16*>(smem + BTOFF_(s, 1));
        const __nv_bfloat16* Bh = reinterpret_cast<const __nv_bfloat16*>(smem + BTOFF_(s, 2));
        const __nv_bfloat16* Bl = reinterpret_cast<const __nv_bfloat16*>(smem + BTOFF_(s, 3));
        #pragma unroll
        for (int ks = 0; ks < KC_; ks += 16) {
            FragA fah[2], fal[2];
            FragB fbh[4], fbl[4];
            #pragma unroll
            for (int mt = 0; mt < 2; mt++) {
                wmma::load_matrix_sync(fah[mt], Ah + (m0 + mt * 16) * LDS_ + ks, LDS_);
                wmma::load_matrix_sync(fal[mt], Al + (m0 + mt * 16) * LDS_ + ks, LDS_);
            }
            #pragma unroll
            for (int nt = 0; nt < 4; nt++) {
                wmma::load_matrix_sync(fbh[nt], Bh + (n0 + nt * 16) * LDS_ + ks, LDS_);
                wmma::load_matrix_sync(fbl[nt], Bl + (n0 + nt * 16) * LDS_ + ks, LDS_);
            }
            #pragma unroll
            for (int mt = 0; mt < 2; mt++)
                #pragma unroll
                for (int nt = 0; nt < 4; nt++) {
                    wmma::mma_sync(acc[mt][nt], fah[mt], fbh[nt], acc[mt][nt]);
                    wmma::mma_sync(acc[mt][nt], fah[mt], fbl[nt], acc[mt][nt]);
                    wmma::mma_sync(acc[mt][nt], fal[mt], fbh[nt], acc[mt][nt]);
                }
        }
        __syncthreads();
    }

    // epilogue: acc -> smem stage -> +bias -> coalesced fp32 stores
    float* Stage = reinterpret_cast<float*>(smem);   // [128][132]
    #pragma unroll
    for (int mt = 0; mt < 2; mt++)
        #pragma unroll
        for (int nt = 0; nt < 4; nt++)
            wmma::store_matrix_sync(Stage + (m0 + mt * 16) * 132 + n0 + nt * 16,
                                    acc[mt][nt], 132, wmma::mem_row_major);
    __syncthreads();

    #pragma unroll
    for (int q = 0; q < 16; q++) {
        int flat = q * 256 + tid;
        int r = flat >> 5, j = flat & 31;
        float4 v = *reinterpret_cast<const float4*>(Stage + r * 132 + j * 4);
        float4 bias = *reinterpret_cast<const float4*>(g_bias + b * D_ + o0 + j * 4);
        v.x += bias.x; v.y += bias.y; v.z += bias.z; v.w += bias.w;
        *reinterpret_cast<float4*>(out + (size_t)(b * T_ + t0 + r) * D_ + o0 + j * 4) = v;
    }
}

// =====================================================================
extern "C" void kernel_launch(void* const* d_in, const int* in_sizes, int n_in,
                              void* d_out, int out_size)
{
    (void)in_sizes; (void)n_in; (void)out_size;
    const float* x    = (const float*)d_in[0];
    const float* Wqkv = (const float*)d_in[1];
    const float* bqkv = (const float*)d_in[2];
    const float* Wout = (const float*)d_in[3];
    const float* bout = (const float*)d_in[4];
    float* out = (float*)d_out;

    cudaFuncSetAttribute(k1_kv_context, cudaFuncAttributeMaxDynamicSharedMemorySize, WSMEM_);
    cudaFuncSetAttribute(k5_out, cudaFuncAttributeMaxDynamicSharedMemorySize, WSMEM_);

    k1_kv_context<<<dim3(NTILE_, H_, B_), 256, WSMEM_>>>(x, Wqkv, bqkv);
    k2_reduce<<<B_ * H_, 256>>>();
    k3_A<<<B_ * H_, 256>>>(Wqkv);
    k3b_pb<<<B_, D_>>>(bqkv);
    k4_E<<<dim3(4, 4, B_), 256>>>(Wout);
    k4b_bias<<<B_, D_>>>(Wout, bout);
    k5_out<<<dim3(NTILE_, 4, B_), 256, WSMEM_>>>(x, out);
}